// round 8
// baseline (speedup 1.0000x reference)
#include <cuda_runtime.h>
#include <cstdint>

#define BSZ   2048
#define NT    49
#define CDIM  384
#define HEADS 12
#define DH    32
#define NN2   (NT * NT)   // 2401
#define MAXNW 64

// ---------------- scratch (device globals; no runtime alloc allowed) -------
__device__ float g_qkv[(size_t)3 * BSZ * HEADS * NT * DH];  // [3][B][H][N][Dh]
__device__ float g_att[(size_t)BSZ * NT * CDIM];            // [B][N][C]
__device__ float g_tbl[169 * HEADS];                        // 16*sigmoid(cpb)
__device__ float g_mrpb[(size_t)MAXNW * HEADS * NN2];       // mask + rpb, [w][h][N*N]

// ---------------- CPB MLP: 169 entries, 2 -> 512 -> 12 ---------------------
__global__ void cpb_kernel(const float* __restrict__ rel_table,
                           const float* __restrict__ w1,
                           const float* __restrict__ b1,
                           const float* __restrict__ w2)
{
    const int e = blockIdx.x;                 // 0..168
    const float x0 = rel_table[e * 2 + 0];
    const float x1 = rel_table[e * 2 + 1];
    __shared__ float hid[512];
    const int t = threadIdx.x;
    hid[t] = fmaxf(w1[t * 2] * x0 + w1[t * 2 + 1] * x1 + b1[t], 0.f);
    __syncthreads();
    const int warp = t >> 5, lane = t & 31;
    if (warp < HEADS) {
        float s = 0.f;
        #pragma unroll
        for (int i = lane; i < 512; i += 32) s += hid[i] * w2[warp * 512 + i];
        #pragma unroll
        for (int o = 16; o; o >>= 1) s += __shfl_xor_sync(0xffffffffu, s, o);
        if (lane == 0) g_tbl[e * HEADS + warp] = 16.f / (1.f + expf(-s));
    }
}

// -------- mask+RPB fuse: g_mrpb[w][h][ij] = mask[w][ij] + g_tbl[idx[ij]][h] -
__global__ void mrpb_kernel(const float* __restrict__ mask,
                            const int* __restrict__ rel_index)
{
    const int wh = blockIdx.x;           // w * HEADS + h
    const int w = wh / HEADS;
    const int h = wh - w * HEADS;
    const float* mrow = mask + (size_t)w * NN2;
    float* out = g_mrpb + (size_t)wh * NN2;
    for (int ij = threadIdx.x; ij < NN2; ij += blockDim.x)
        out[ij] = mrow[ij] + g_tbl[rel_index[ij] * HEADS + h];
}

// ---------------- tf32 helpers ---------------------------------------------
__device__ __forceinline__ unsigned tf32_rna(float x) {
    unsigned u;
    asm("cvt.rna.tf32.f32 %0, %1;" : "=r"(u) : "f"(x));
    return u;
}

__device__ __forceinline__ void mma_tf32(float c[4], const unsigned a[4],
                                         const unsigned b[2]) {
    asm volatile(
        "mma.sync.aligned.m16n8k8.row.col.f32.tf32.tf32.f32 "
        "{%0,%1,%2,%3}, {%4,%5,%6,%7}, {%8,%9}, {%0,%1,%2,%3};"
        : "+f"(c[0]), "+f"(c[1]), "+f"(c[2]), "+f"(c[3])
        : "r"(a[0]), "r"(a[1]), "r"(a[2]), "r"(a[3]), "r"(b[0]), "r"(b[1]));
}

// ---------------- tensor-core GEMM (3xTF32): C[m,n] = sum_k A[m,k]*Bw[n,k] --
// MODE 0: A = x, out scattered to g_qkv with q/v bias
// MODE 1: A = g_att, out = Cout (+ bias bq)
// Block tile 128x128; 8 warps (2x4), warp tile 64x32.
// Two-stage pipeline, k-depth 8 per stage. Smem: [k][col] float2{hi,lo tf32},
// stride 132 float2, XOR swizzle col ^= ((k>>2)&1)*4. A warp's commit lanes
// all share one k-coset (kq = (tid>>7)*4) -> STS.64 and LDS.64 conflict-free.
// Inner loop holds all B fragments (16 regs) and streams A per-mt to keep
// register pressure under the 128-reg / 2-blocks-per-SM budget.
#define S2 132

template<int MODE>
__global__ __launch_bounds__(256, 2)
void sgemm_tc_kernel(const float* __restrict__ Aparam,
                     const float* __restrict__ Bw,
                     const float* __restrict__ bq,
                     const float* __restrict__ bv,
                     float* __restrict__ Cout,
                     int K)
{
    const float* A = (MODE == 0) ? Aparam : g_att;
    const int n0 = blockIdx.x * 128;       // x = n-blocks (few) -> A-band reuse
    const int m0 = blockIdx.y * 128;

    __shared__ float2 Asm[2][8 * S2];
    __shared__ float2 Bsm[2][8 * S2];

    const int tid  = threadIdx.x;
    const int warp = tid >> 5;
    const int lane = tid & 31;
    const int wm   = warp >> 2;           // 0..1  -> 64 rows
    const int wn   = warp & 3;            // 0..3  -> 32 cols
    const int g    = lane >> 2;           // 0..7
    const int tig  = lane & 3;            // 0..3

    // global-load / commit mapping
    const int r_ = tid & 127;             // row within tile
    const int kq = (tid >> 7) << 2;       // 0 or 4 (k base); swizzle c == kq
    const int sc = r_ ^ kq;               // committed column (fixed per thread)
    const float* agp = &A [(size_t)(m0 + r_) * K + kq];
    const float* bgp = &Bw[(size_t)(n0 + r_) * K + kq];

    float acc[4][4][4];
    #pragma unroll
    for (int mt = 0; mt < 4; mt++)
        #pragma unroll
        for (int nt = 0; nt < 4; nt++)
            #pragma unroll
            for (int r = 0; r < 4; r++) acc[mt][nt][r] = 0.f;

    const int KT = K / 8;                 // stages
    float4 pa, pb;

    // prologue: stage 0 -> buf0, prefetch stage 1
    pa = *(const float4*)agp;
    pb = *(const float4*)bgp;
    #pragma unroll
    for (int j = 0; j < 4; j++) {
        const float avj = ((const float*)&pa)[j];
        const float bvj = ((const float*)&pb)[j];
        const unsigned ah = tf32_rna(avj);
        const unsigned bh = tf32_rna(bvj);
        Asm[0][(kq + j) * S2 + sc] = make_float2(
            __uint_as_float(ah), __uint_as_float(tf32_rna(avj - __uint_as_float(ah))));
        Bsm[0][(kq + j) * S2 + sc] = make_float2(
            __uint_as_float(bh), __uint_as_float(tf32_rna(bvj - __uint_as_float(bh))));
    }
    pa = *(const float4*)(agp + 8);
    pb = *(const float4*)(bgp + 8);
    __syncthreads();

    for (int kt = 0; kt < KT; ++kt) {
        // commit stage kt+1 (overlaps compute of stage kt)
        if (kt + 1 < KT) {
            float2* As = Asm[(kt + 1) & 1];
            float2* Bs = Bsm[(kt + 1) & 1];
            #pragma unroll
            for (int j = 0; j < 4; j++) {
                const float avj = ((const float*)&pa)[j];
                const float bvj = ((const float*)&pb)[j];
                const unsigned ah = tf32_rna(avj);
                const unsigned bh = tf32_rna(bvj);
                As[(kq + j) * S2 + sc] = make_float2(
                    __uint_as_float(ah),
                    __uint_as_float(tf32_rna(avj - __uint_as_float(ah))));
                Bs[(kq + j) * S2 + sc] = make_float2(
                    __uint_as_float(bh),
                    __uint_as_float(tf32_rna(bvj - __uint_as_float(bh))));
            }
        }
        // prefetch stage kt+2
        if (kt + 2 < KT) {
            pa = *(const float4*)(agp + (kt + 2) * 8);
            pb = *(const float4*)(bgp + (kt + 2) * 8);
        }

        // compute stage kt: B fragments resident, A streamed per-mt
        {
            const float2* As = Asm[kt & 1];
            const float2* Bs = Bsm[kt & 1];
            const int row0 = tig * S2;            // k rows 0..3: coset 0
            const int row4 = (tig + 4) * S2;      // k rows 4..7: coset 4

            unsigned bh[4][2], bl[4][2];
            #pragma unroll
            for (int nt = 0; nt < 4; nt++) {
                const int nb = wn * 32 + nt * 8 + g;
                const float2 b0 = Bs[row0 + nb];
                const float2 b1 = Bs[row4 + (nb ^ 4)];
                bh[nt][0] = __float_as_uint(b0.x); bh[nt][1] = __float_as_uint(b1.x);
                bl[nt][0] = __float_as_uint(b0.y); bl[nt][1] = __float_as_uint(b1.y);
            }
            #pragma unroll
            for (int mt = 0; mt < 4; mt++) {
                const int mb = wm * 64 + mt * 16 + g;
                const float2 a00 = As[row0 + mb];
                const float2 a01 = As[row0 + (mb + 8)];
                const float2 a10 = As[row4 + (mb ^ 4)];
                const float2 a11 = As[row4 + ((mb + 8) ^ 4)];
                const unsigned ah[4] = {__float_as_uint(a00.x), __float_as_uint(a01.x),
                                        __float_as_uint(a10.x), __float_as_uint(a11.x)};
                const unsigned al[4] = {__float_as_uint(a00.y), __float_as_uint(a01.y),
                                        __float_as_uint(a10.y), __float_as_uint(a11.y)};
                #pragma unroll
                for (int nt = 0; nt < 4; nt++) {
                    mma_tf32(acc[mt][nt], ah, bh[nt]);   // hi*hi
                    mma_tf32(acc[mt][nt], ah, bl[nt]);   // hi*lo
                    mma_tf32(acc[mt][nt], al, bh[nt]);   // lo*hi
                }
            }
        }
        __syncthreads();
    }

    // ---------------- epilogue ----------------
    #pragma unroll
    for (int nt = 0; nt < 4; nt++) {
        const int cc = n0 + wn * 32 + nt * 8 + tig * 2;   // even column
        int s = 0, h = 0, d = 0;
        float2 bz = make_float2(0.f, 0.f);
        if (MODE == 0) {
            s  = cc / CDIM;
            const int rr = cc - s * CDIM;
            h  = rr >> 5;
            d  = rr & 31;
            if (s == 0)      bz = *(const float2*)&bq[rr];
            else if (s == 2) bz = *(const float2*)&bv[rr];
        } else {
            bz = *(const float2*)&bq[cc];
        }
        #pragma unroll
        for (int mt = 0; mt < 4; mt++) {
            #pragma unroll
            for (int half = 0; half < 2; half++) {
                const int m = m0 + wm * 64 + mt * 16 + g + half * 8;
                float2 o;
                o.x = acc[mt][nt][half * 2 + 0] + bz.x;
                o.y = acc[mt][nt][half * 2 + 1] + bz.y;
                if (MODE == 0) {
                    const int bb = m / NT;
                    const int nn = m - bb * NT;
                    const size_t off =
                        ((((size_t)s * BSZ + bb) * HEADS + h) * NT + nn) * DH + d;
                    *(float2*)&g_qkv[off] = o;
                } else {
                    *(float2*)&Cout[(size_t)m * CDIM + cc] = o;
                }
            }
        }
    }
}

// ---------------- attention: one block per (b, h) --------------------------
// score(i,j) = (q_i . k_j) * sinvq[i]*ls * sinvk[j] + (mask+rpb)[i,j]
// (separable normalization applied at the epilogue; no normalize pass)
__global__ __launch_bounds__(256)
void attn_kernel(const float* __restrict__ logit_scale, int nW)
{
    const int bh = blockIdx.x;
    const int b = bh / HEADS;
    const int h = bh - b * HEADS;
    const int w = b % nW;

    __shared__ float sq[56 * 33];   // padded rows: junk rows 49..55 read OK
    __shared__ float sk[64 * 33];   // padded so j+32 reads never fault
    __shared__ float sv[NT * 33];
    __shared__ float sS[56 * 50];   // padded rows for batched PV reads
    __shared__ float sinv[128];     // [0..NT): q rows, [NT..NT+64): k rows (padded)

    const int tid = threadIdx.x;
    const size_t hd = (size_t)(b * HEADS + h) * NT * DH;
    const size_t SP = (size_t)BSZ * HEADS * NT * DH;
    const float* gq = g_qkv + hd;
    const float* gk = g_qkv + SP + hd;
    const float* gv = g_qkv + 2 * SP + hd;

    // vectorized loads: NT*DH = 1568 floats = 392 float4
    for (int i = tid; i < (NT * DH) / 4; i += 256) {
        const int r = i >> 3;                // (i*4)>>5
        const int d = (i & 7) * 4;
        const float4 q4 = *(const float4*)&gq[i * 4];
        const float4 k4 = *(const float4*)&gk[i * 4];
        const float4 v4 = *(const float4*)&gv[i * 4];
        sq[r * 33 + d] = q4.x; sq[r * 33 + d + 1] = q4.y;
        sq[r * 33 + d + 2] = q4.z; sq[r * 33 + d + 3] = q4.w;
        sk[r * 33 + d] = k4.x; sk[r * 33 + d + 1] = k4.y;
        sk[r * 33 + d + 2] = k4.z; sk[r * 33 + d + 3] = k4.w;
        sv[r * 33 + d] = v4.x; sv[r * 33 + d + 1] = v4.y;
        sv[r * 33 + d + 2] = v4.z; sv[r * 33 + d + 3] = v4.w;
    }
    __syncthreads();

    const int warp = tid >> 5, lane = tid & 31;
    const float ls = __expf(fminf(logit_scale[h], 4.6051702f));   // log(100)

    // row inverse norms of q and k
    for (int r = warp; r < 2 * NT; r += 8) {
        const float* p = (r < NT) ? &sq[r * 33] : &sk[(r - NT) * 33];
        const float v = p[lane];
        float s = v * v;
        #pragma unroll
        for (int o = 16; o; o >>= 1) s += __shfl_xor_sync(0xffffffffu, s, o);
        if (lane == 0) sinv[r] = 1.f / (sqrtf(s) + 1e-6f);
    }
    __syncthreads();

    // ---- scores: each warp owns rows {warp, warp+8, ...} (<=7), batched ----
    {
        float a0[7], a1[7];
        #pragma unroll
        for (int r = 0; r < 7; r++) { a0[r] = 0.f; a1[r] = 0.f; }
        #pragma unroll
        for (int d = 0; d < DH; d++) {
            const float k0 = sk[lane * 33 + d];
            const float k1 = sk[(lane + 32) * 33 + d];
            #pragma unroll
            for (int r = 0; r < 7; r++) {
                const float qv = sq[(warp + r * 8) * 33 + d];  // padded rows junk
                a0[r] = fmaf(qv, k0, a0[r]);
                a1[r] = fmaf(qv, k1, a1[r]);
            }
        }
        const float sk0 = sinv[NT + lane];                      // k scale, col j0
        const float sk1 = sinv[NT + lane + 32];                 // col j1 (guarded use)
        const float* bias = g_mrpb + ((size_t)w * HEADS + h) * NN2;
        #pragma unroll
        for (int r = 0; r < 7; r++) {
            const int i = warp + r * 8;
            if (i < NT) {
                const float siq = sinv[i] * ls;
                const int ij0 = i * NT + lane;
                sS[i * 50 + lane] = a0[r] * siq * sk0 + bias[ij0];
                if (lane + 32 < NT)
                    sS[i * 50 + lane + 32] = a1[r] * siq * sk1 + bias[ij0 + 32];
            }
        }
    }
    __syncthreads();

    // softmax per row (reference: e / (sum + 1e-6))
    for (int i = warp; i < NT; i += 8) {
        const float v0 = sS[i * 50 + lane];
        const float v1 = (lane + 32 < NT) ? sS[i * 50 + lane + 32] : -1e30f;
        float mx = fmaxf(v0, v1);
        #pragma unroll
        for (int o = 16; o; o >>= 1) mx = fmaxf(mx, __shfl_xor_sync(0xffffffffu, mx, o));
        const float e0 = __expf(v0 - mx);
        const float e1 = (lane + 32 < NT) ? __expf(v1 - mx) : 0.f;
        float s = e0 + e1;
        #pragma unroll
        for (int o = 16; o; o >>= 1) s += __shfl_xor_sync(0xffffffffu, s, o);
        const float inv = 1.f / (s + 1e-6f);
        sS[i * 50 + lane] = e0 * inv;
        if (lane + 32 < NT) sS[i * 50 + lane + 32] = e1 * inv;
    }
    __syncthreads();

    // ---- PV: batched over the warp's rows; lane = d ----
    {
        float av[7];
        #pragma unroll
        for (int r = 0; r < 7; r++) av[r] = 0.f;
        for (int j = 0; j < NT; j++) {
            const float vv = sv[j * 33 + lane];
            #pragma unroll
            for (int r = 0; r < 7; r++)
                av[r] = fmaf(sS[(warp + r * 8) * 50 + j], vv, av[r]);
        }
        #pragma unroll
        for (int r = 0; r < 7; r++) {
            const int i = warp + r * 8;
            if (i < NT)
                g_att[(size_t)(b * NT + i) * CDIM + h * DH + lane] = av[r];
        }
    }
}

// ---------------- launch ----------------------------------------------------
extern "C" void kernel_launch(void* const* d_in, const int* in_sizes, int n_in,
                              void* d_out, int out_size)
{
    const float* x           = (const float*)d_in[0];
    const float* mask        = (const float*)d_in[1];
    const float* qkv_w       = (const float*)d_in[2];
    const float* q_bias      = (const float*)d_in[3];
    const float* v_bias      = (const float*)d_in[4];
    const float* logit_scale = (const float*)d_in[5];
    const float* cpb_w1      = (const float*)d_in[6];
    const float* cpb_b1      = (const float*)d_in[7];
    const float* cpb_w2      = (const float*)d_in[8];
    const float* proj_w      = (const float*)d_in[9];
    const float* proj_b      = (const float*)d_in[10];
    const float* rel_table   = (const float*)d_in[11];
    const int*   rel_index   = (const int*)d_in[12];
    float* out = (float*)d_out;

    const int nW = in_sizes[1] / (NT * NT);   // 64 for this problem

    cpb_kernel<<<169, 512>>>(rel_table, cpb_w1, cpb_b1, cpb_w2);
    mrpb_kernel<<<nW * HEADS, 256>>>(mask, rel_index);

    // grid.x = n-blocks (few) so co-resident blocks share the same A band (L2)
    dim3 g1((3 * CDIM) / 128, (BSZ * NT) / 128);
    sgemm_tc_kernel<0><<<g1, 256>>>(x, qkv_w, q_bias, v_bias, nullptr, CDIM);

    attn_kernel<<<BSZ * HEADS, 256>>>(logit_scale, nW);

    dim3 g2(CDIM / 128, (BSZ * NT) / 128);
    sgemm_tc_kernel<1><<<g2, 256>>>(nullptr, proj_w, proj_b, nullptr, out, CDIM);
}

// round 10
// speedup vs baseline: 1.4297x; 1.4297x over previous
#include <cuda_runtime.h>
#include <cstdint>

#define BSZ   2048
#define NT    49
#define CDIM  384
#define HEADS 12
#define DH    32
#define NN2   (NT * NT)   // 2401
#define MAXNW 64

// ---------------- scratch (device globals; no runtime alloc allowed) -------
__device__ float g_qkv[(size_t)3 * BSZ * HEADS * NT * DH];  // [3][B][H][N][Dh]
__device__ float g_att[(size_t)BSZ * NT * CDIM];            // [B][N][C]
__device__ float g_tbl[169 * HEADS];                        // 16*sigmoid(cpb)
__device__ float g_mrpb[(size_t)MAXNW * HEADS * NN2];       // mask + rpb, [w][h][N*N]

// ---------------- CPB MLP: 169 entries, 2 -> 512 -> 12 ---------------------
__global__ void cpb_kernel(const float* __restrict__ rel_table,
                           const float* __restrict__ w1,
                           const float* __restrict__ b1,
                           const float* __restrict__ w2)
{
    const int e = blockIdx.x;                 // 0..168
    const float x0 = rel_table[e * 2 + 0];
    const float x1 = rel_table[e * 2 + 1];
    __shared__ float hid[512];
    const int t = threadIdx.x;
    hid[t] = fmaxf(w1[t * 2] * x0 + w1[t * 2 + 1] * x1 + b1[t], 0.f);
    __syncthreads();
    const int warp = t >> 5, lane = t & 31;
    if (warp < HEADS) {
        float s = 0.f;
        #pragma unroll
        for (int i = lane; i < 512; i += 32) s += hid[i] * w2[warp * 512 + i];
        #pragma unroll
        for (int o = 16; o; o >>= 1) s += __shfl_xor_sync(0xffffffffu, s, o);
        if (lane == 0) g_tbl[e * HEADS + warp] = 16.f / (1.f + expf(-s));
    }
}

// -------- mask+RPB fuse: g_mrpb[w][h][ij] = mask[w][ij] + g_tbl[idx[ij]][h] -
__global__ void mrpb_kernel(const float* __restrict__ mask,
                            const int* __restrict__ rel_index)
{
    const int wh = blockIdx.x;           // w * HEADS + h
    const int w = wh / HEADS;
    const int h = wh - w * HEADS;
    const float* mrow = mask + (size_t)w * NN2;
    float* out = g_mrpb + (size_t)wh * NN2;
    for (int ij = threadIdx.x; ij < NN2; ij += blockDim.x)
        out[ij] = mrow[ij] + g_tbl[rel_index[ij] * HEADS + h];
}

// ---------------- bf16 split helpers ----------------------------------------
// split2: two fp32 -> uint2{bf16x2 hi (k-even low, k-odd high), bf16x2 lo}
__device__ __forceinline__ uint2 split2(float x0, float x1) {
    unsigned hp, lp;
    asm("cvt.rn.bf16x2.f32 %0, %1, %2;" : "=r"(hp) : "f"(x1), "f"(x0));
    const float l0 = x0 - __uint_as_float(hp << 16);
    const float l1 = x1 - __uint_as_float(hp & 0xffff0000u);
    asm("cvt.rn.bf16x2.f32 %0, %1, %2;" : "=r"(lp) : "f"(l1), "f"(l0));
    return make_uint2(hp, lp);
}

__device__ __forceinline__ void mma_bf16(float c[4], const unsigned a[4],
                                         const unsigned b[2]) {
    asm volatile(
        "mma.sync.aligned.m16n8k16.row.col.f32.bf16.bf16.f32 "
        "{%0,%1,%2,%3}, {%4,%5,%6,%7}, {%8,%9}, {%0,%1,%2,%3};"
        : "+f"(c[0]), "+f"(c[1]), "+f"(c[2]), "+f"(c[3])
        : "r"(a[0]), "r"(a[1]), "r"(a[2]), "r"(a[3]), "r"(b[0]), "r"(b[1]));
}

// ---------------- tensor-core GEMM (4xBF16): C[m,n] = sum_k A[m,k]*Bw[n,k] --
// MODE 0: A = x, out scattered to g_qkv with q/v bias
// MODE 1: A = g_att, out = Cout (+ bias bq)
// Block tile 128x128; 8 warps (2x4), warp tile 64x32.
// Two-stage pipeline, k-depth 16 per stage (8 k-pair rows). Smem: [kp][col] of
// uint2{bf16x2 hi, bf16x2 lo}, stride 132, XOR swizzle col ^= ((kp>>2)&1)*4.
// A warp's commit lanes share one kp-coset (kpb = (tid>>7)*4) -> STS.64 and
// LDS.64 conflict-free (isomorphic to the verified tf32 layout).
#define S2 132

template<int MODE>
__global__ __launch_bounds__(256, 2)
void sgemm_tc_kernel(const float* __restrict__ Aparam,
                     const float* __restrict__ Bw,
                     const float* __restrict__ bq,
                     const float* __restrict__ bv,
                     float* __restrict__ Cout,
                     int K)
{
    const float* A = (MODE == 0) ? Aparam : g_att;
    const int n0 = blockIdx.x * 128;       // x = n-blocks (few) -> A-band reuse
    const int m0 = blockIdx.y * 128;

    __shared__ uint2 Asm[2][8 * S2];
    __shared__ uint2 Bsm[2][8 * S2];

    const int tid  = threadIdx.x;
    const int warp = tid >> 5;
    const int lane = tid & 31;
    const int wm   = warp >> 2;           // 0..1  -> 64 rows
    const int wn   = warp & 3;            // 0..3  -> 32 cols
    const int g    = lane >> 2;           // 0..7
    const int tig  = lane & 3;            // 0..3

    // global-load / commit mapping: thread covers k [kq8, kq8+8) of row r_
    const int r_  = tid & 127;            // row within tile
    const int kq8 = (tid >> 7) << 3;      // 0 or 8
    const int kpb = kq8 >> 1;             // kp base 0 or 4 == coset
    const int sc  = r_ ^ kpb;             // committed column (fixed per thread)
    const float* agp = &A [(size_t)(m0 + r_) * K + kq8];
    const float* bgp = &Bw[(size_t)(n0 + r_) * K + kq8];

    float acc[4][4][4];
    #pragma unroll
    for (int mt = 0; mt < 4; mt++)
        #pragma unroll
        for (int nt = 0; nt < 4; nt++)
            #pragma unroll
            for (int r = 0; r < 4; r++) acc[mt][nt][r] = 0.f;

    const int KT = K / 16;                // stages (24 for K=384)
    float4 pa0, pa1, pb0, pb1;

    // prologue: stage 0 -> buf0, prefetch stage 1
    pa0 = *(const float4*)agp;        pa1 = *(const float4*)(agp + 4);
    pb0 = *(const float4*)bgp;        pb1 = *(const float4*)(bgp + 4);
    #pragma unroll
    for (int j = 0; j < 2; j++) {
        const float* af = j ? (const float*)&pa1 : (const float*)&pa0;
        const float* bf = j ? (const float*)&pb1 : (const float*)&pb0;
        Asm[0][(kpb + j * 2 + 0) * S2 + sc] = split2(af[0], af[1]);
        Asm[0][(kpb + j * 2 + 1) * S2 + sc] = split2(af[2], af[3]);
        Bsm[0][(kpb + j * 2 + 0) * S2 + sc] = split2(bf[0], bf[1]);
        Bsm[0][(kpb + j * 2 + 1) * S2 + sc] = split2(bf[2], bf[3]);
    }
    pa0 = *(const float4*)(agp + 16); pa1 = *(const float4*)(agp + 20);
    pb0 = *(const float4*)(bgp + 16); pb1 = *(const float4*)(bgp + 20);
    __syncthreads();

    for (int kt = 0; kt < KT; ++kt) {
        // commit stage kt+1 (overlaps compute of stage kt)
        if (kt + 1 < KT) {
            uint2* As = Asm[(kt + 1) & 1];
            uint2* Bs = Bsm[(kt + 1) & 1];
            #pragma unroll
            for (int j = 0; j < 2; j++) {
                const float* af = j ? (const float*)&pa1 : (const float*)&pa0;
                const float* bf = j ? (const float*)&pb1 : (const float*)&pb0;
                As[(kpb + j * 2 + 0) * S2 + sc] = split2(af[0], af[1]);
                As[(kpb + j * 2 + 1) * S2 + sc] = split2(af[2], af[3]);
                Bs[(kpb + j * 2 + 0) * S2 + sc] = split2(bf[0], bf[1]);
                Bs[(kpb + j * 2 + 1) * S2 + sc] = split2(bf[2], bf[3]);
            }
        }
        // prefetch stage kt+2
        if (kt + 2 < KT) {
            const float* ap = agp + (kt + 2) * 16;
            const float* bp = bgp + (kt + 2) * 16;
            pa0 = *(const float4*)ap;       pa1 = *(const float4*)(ap + 4);
            pb0 = *(const float4*)bp;       pb1 = *(const float4*)(bp + 4);
        }

        // compute stage kt: B fragments resident, A streamed per-mt
        {
            const uint2* As = Asm[kt & 1];
            const uint2* Bs = Bsm[kt & 1];
            const int row0 = tig * S2;            // kp 0..3: coset 0
            const int row4 = (tig + 4) * S2;      // kp 4..7: coset 4

            unsigned bhv[4][2], blv[4][2];
            #pragma unroll
            for (int nt = 0; nt < 4; nt++) {
                const int nb = wn * 32 + nt * 8 + g;
                const uint2 b0 = Bs[row0 + nb];
                const uint2 b1 = Bs[row4 + (nb ^ 4)];
                bhv[nt][0] = b0.x; bhv[nt][1] = b1.x;
                blv[nt][0] = b0.y; blv[nt][1] = b1.y;
            }
            #pragma unroll
            for (int mt = 0; mt < 4; mt++) {
                const int mb = wm * 64 + mt * 16 + g;
                const uint2 a00 = As[row0 + mb];
                const uint2 a01 = As[row0 + (mb + 8)];
                const uint2 a10 = As[row4 + (mb ^ 4)];
                const uint2 a11 = As[row4 + ((mb + 8) ^ 4)];
                const unsigned ah[4] = {a00.x, a01.x, a10.x, a11.x};
                const unsigned al[4] = {a00.y, a01.y, a10.y, a11.y};
                #pragma unroll
                for (int nt = 0; nt < 4; nt++) {
                    mma_bf16(acc[mt][nt], ah, bhv[nt]);   // hi*hi
                    mma_bf16(acc[mt][nt], ah, blv[nt]);   // hi*lo
                    mma_bf16(acc[mt][nt], al, bhv[nt]);   // lo*hi
                    mma_bf16(acc[mt][nt], al, blv[nt]);   // lo*lo
                }
            }
        }
        __syncthreads();
    }

    // ---------------- epilogue ----------------
    #pragma unroll
    for (int nt = 0; nt < 4; nt++) {
        const int cc = n0 + wn * 32 + nt * 8 + tig * 2;   // even column
        int s = 0, h = 0, d = 0;
        float2 bz = make_float2(0.f, 0.f);
        if (MODE == 0) {
            s  = cc / CDIM;
            const int rr = cc - s * CDIM;
            h  = rr >> 5;
            d  = rr & 31;
            if (s == 0)      bz = *(const float2*)&bq[rr];
            else if (s == 2) bz = *(const float2*)&bv[rr];
        } else {
            bz = *(const float2*)&bq[cc];
        }
        #pragma unroll
        for (int mt = 0; mt < 4; mt++) {
            #pragma unroll
            for (int half = 0; half < 2; half++) {
                const int m = m0 + wm * 64 + mt * 16 + g + half * 8;
                float2 o;
                o.x = acc[mt][nt][half * 2 + 0] + bz.x;
                o.y = acc[mt][nt][half * 2 + 1] + bz.y;
                if (MODE == 0) {
                    const int bb = m / NT;
                    const int nn = m - bb * NT;
                    const size_t off =
                        ((((size_t)s * BSZ + bb) * HEADS + h) * NT + nn) * DH + d;
                    *(float2*)&g_qkv[off] = o;
                } else {
                    *(float2*)&Cout[(size_t)m * CDIM + cc] = o;
                }
            }
        }
    }
}

// ---------------- attention: one block per (b, h) --------------------------
// Vectorized LDS: q/k/v stride 36 (16B-aligned, conflict-free LDS.128),
// scores stride 52. sv rows 49..51 and sS cols 49..51 zeroed so the x4
// unrolled PV tail is exact. score(i,j) = (q.k)*sinvq[i]*ls*sinvk[j] + bias.
#define SQK 36
#define SSW 52
__global__ __launch_bounds__(256)
void attn_kernel(const float* __restrict__ logit_scale, int nW)
{
    const int bh = blockIdx.x;
    const int b = bh / HEADS;
    const int h = bh - b * HEADS;
    const int w = b % nW;

    __shared__ float sq[56 * SQK];  // rows 49..55 junk (guarded at store)
    __shared__ float sk[64 * SQK];  // rows 49..63 junk (guarded at store)
    __shared__ float sv[52 * SQK];  // rows 49..51 zeroed
    __shared__ float sS[56 * SSW];  // cols 49..51 zeroed; rows 49..55 junk
    __shared__ float sinv[128];     // [0..NT) q rows, [NT..NT+64) k rows (padded)

    const int tid = threadIdx.x;
    const size_t hd = (size_t)(b * HEADS + h) * NT * DH;
    const size_t SP = (size_t)BSZ * HEADS * NT * DH;
    const float* gq = g_qkv + hd;
    const float* gk = g_qkv + SP + hd;
    const float* gv = g_qkv + 2 * SP + hd;

    // zero sv pad rows 49..51 (96 floats)
    if (tid < 96) sv[(49 + tid / 32) * SQK + (tid & 31)] = 0.f;

    // vectorized loads: NT*DH = 1568 floats = 392 float4
    for (int i = tid; i < (NT * DH) / 4; i += 256) {
        const int r = i >> 3;                // (i*4)>>5
        const int d = (i & 7) * 4;
        const float4 q4 = *(const float4*)&gq[i * 4];
        const float4 k4 = *(const float4*)&gk[i * 4];
        const float4 v4 = *(const float4*)&gv[i * 4];
        *(float4*)&sq[r * SQK + d] = q4;
        *(float4*)&sk[r * SQK + d] = k4;
        *(float4*)&sv[r * SQK + d] = v4;
    }
    __syncthreads();

    const int warp = tid >> 5, lane = tid & 31;
    const float ls = __expf(fminf(logit_scale[h], 4.6051702f));   // log(100)

    // row inverse norms of q and k
    for (int r = warp; r < 2 * NT; r += 8) {
        const float* p = (r < NT) ? &sq[r * SQK] : &sk[(r - NT) * SQK];
        const float v = p[lane];
        float s = v * v;
        #pragma unroll
        for (int o = 16; o; o >>= 1) s += __shfl_xor_sync(0xffffffffu, s, o);
        if (lane == 0) sinv[r] = 1.f / (sqrtf(s) + 1e-6f);
    }
    __syncthreads();

    // ---- scores: warp owns rows {warp, warp+8, ...}; d-loop in float4 ----
    {
        float a0[7], a1[7];
        #pragma unroll
        for (int r = 0; r < 7; r++) { a0[r] = 0.f; a1[r] = 0.f; }
        #pragma unroll
        for (int d = 0; d < DH; d += 4) {
            const float4 k0 = *(const float4*)&sk[lane * SQK + d];
            const float4 k1 = *(const float4*)&sk[(lane + 32) * SQK + d];
            #pragma unroll
            for (int r = 0; r < 7; r++) {
                const float4 q4 = *(const float4*)&sq[(warp + r * 8) * SQK + d];
                a0[r] = fmaf(q4.x, k0.x, fmaf(q4.y, k0.y,
                        fmaf(q4.z, k0.z, fmaf(q4.w, k0.w, a0[r]))));
                a1[r] = fmaf(q4.x, k1.x, fmaf(q4.y, k1.y,
                        fmaf(q4.z, k1.z, fmaf(q4.w, k1.w, a1[r]))));
            }
        }
        const float sk0 = sinv[NT + lane];                      // k scale, col j0
        const float sk1 = sinv[NT + lane + 32];                 // col j1 (guarded use)
        const float* bias = g_mrpb + ((size_t)w * HEADS + h) * NN2;
        #pragma unroll
        for (int r = 0; r < 7; r++) {
            const int i = warp + r * 8;
            if (i < NT) {
                const float siq = sinv[i] * ls;
                const int ij0 = i * NT + lane;
                sS[i * SSW + lane] = a0[r] * siq * sk0 + bias[ij0];
                if (lane + 32 < NT)
                    sS[i * SSW + lane + 32] = a1[r] * siq * sk1 + bias[ij0 + 32];
            }
        }
    }
    __syncthreads();

    // softmax per row (reference: e / (sum + 1e-6)); also zero pad cols 49..51
    for (int i = warp; i < NT; i += 8) {
        const float v0 = sS[i * SSW + lane];
        const float v1 = (lane + 32 < NT) ? sS[i * SSW + lane + 32] : -1e30f;
        float mx = fmaxf(v0, v1);
        #pragma unroll
        for (int o = 16; o; o >>= 1) mx = fmaxf(mx, __shfl_xor_sync(0xffffffffu, mx, o));
        const float e0 = __expf(v0 - mx);
        const float e1 = (lane + 32 < NT) ? __expf(v1 - mx) : 0.f;
        float s = e0 + e1;
        #pragma unroll
        for (int o = 16; o; o >>= 1) s += __shfl_xor_sync(0xffffffffu, s, o);
        const float inv = 1.f / (s + 1e-6f);
        sS[i * SSW + lane] = e0 * inv;
        if (lane + 32 < SSW)
            sS[i * SSW + lane + 32] = (lane + 32 < NT) ? e1 * inv : 0.f;
    }
    __syncthreads();

    // ---- PV: j-loop in groups of 4; sS read as float4 broadcast ----
    {
        float av[7];
        #pragma unroll
        for (int r = 0; r < 7; r++) av[r] = 0.f;
        #pragma unroll
        for (int j = 0; j < 52; j += 4) {
            const float vv0 = sv[(j + 0) * SQK + lane];
            const float vv1 = sv[(j + 1) * SQK + lane];
            const float vv2 = sv[(j + 2) * SQK + lane];
            const float vv3 = sv[(j + 3) * SQK + lane];
            #pragma unroll
            for (int r = 0; r < 7; r++) {
                const float4 p4 = *(const float4*)&sS[(warp + r * 8) * SSW + j];
                av[r] = fmaf(p4.x, vv0, fmaf(p4.y, vv1,
                        fmaf(p4.z, vv2, fmaf(p4.w, vv3, av[r]))));
            }
        }
        #pragma unroll
        for (int r = 0; r < 7; r++) {
            const int i = warp + r * 8;
            if (i < NT)
                g_att[(size_t)(b * NT + i) * CDIM + h * DH + lane] = av[r];
        }
    }
}

// ---------------- launch ----------------------------------------------------
extern "C" void kernel_launch(void* const* d_in, const int* in_sizes, int n_in,
                              void* d_out, int out_size)
{
    const float* x           = (const float*)d_in[0];
    const float* mask        = (const float*)d_in[1];
    const float* qkv_w       = (const float*)d_in[2];
    const float* q_bias      = (const float*)d_in[3];
    const float* v_bias      = (const float*)d_in[4];
    const float* logit_scale = (const float*)d_in[5];
    const float* cpb_w1      = (const float*)d_in[6];
    const float* cpb_b1      = (const float*)d_in[7];
    const float* cpb_w2      = (const float*)d_in[8];
    const float* proj_w      = (const float*)d_in[9];
    const float* proj_b      = (const float*)d_in[10];
    const float* rel_table   = (const float*)d_in[11];
    const int*   rel_index   = (const int*)d_in[12];
    float* out = (float*)d_out;

    const int nW = in_sizes[1] / (NT * NT);   // 64 for this problem

    cpb_kernel<<<169, 512>>>(rel_table, cpb_w1, cpb_b1, cpb_w2);
    mrpb_kernel<<<nW * HEADS, 256>>>(mask, rel_index);

    // grid.x = n-blocks (few) so co-resident blocks share the same A band (L2)
    dim3 g1((3 * CDIM) / 128, (BSZ * NT) / 128);
    sgemm_tc_kernel<0><<<g1, 256>>>(x, qkv_w, q_bias, v_bias, nullptr, CDIM);

    attn_kernel<<<BSZ * HEADS, 256>>>(logit_scale, nW);

    dim3 g2(CDIM / 128, (BSZ * NT) / 128);
    sgemm_tc_kernel<1><<<g2, 256>>>(nullptr, proj_w, proj_b, nullptr, out, CDIM);
}